// round 5
// baseline (speedup 1.0000x reference)
#include <cuda_runtime.h>
#include <math.h>

#define B_ 16
#define T_ 32
#define W_ 128
#define D_ 1024

#define NEG_INF __int_as_float(0xff800000)

// Scratch (device globals: no allocation allowed in kernel_launch)
__device__ float g_qw[B_ * D_];          // source @ W_word   [B,D]
__device__ float g_qt[B_ * D_];          // source @ W_turn   [B,D]
__device__ float g_cw[B_ * T_ * D_];     // word-context      [B,T,D]
__device__ float g_ts[B_ * T_];          // turn scores       [B,T]

// ---------------------------------------------------------------------------
// Kernel 0: zero the projection accumulators (proj uses atomicAdd)
// ---------------------------------------------------------------------------
__global__ void zero_q_kernel() {
    int i = blockIdx.x * 1024 + threadIdx.x;   // grid 16 x 1024 = 16384 = B_*D_
    g_qw[i] = 0.f;
    g_qt[i] = 0.f;
}

// ---------------------------------------------------------------------------
// Kernel 1: q = source @ W  for both W_word and W_turn.
// Grid: (D_/256 j-chunks, D_/64 i-chunks, 2 matrices), 256 threads.
// Each thread owns one output column j for a 64-wide slice of i, accumulating
// all 16 batches in registers; W is read exactly once chip-wide.
// ---------------------------------------------------------------------------
__global__ __launch_bounds__(256) void proj_kernel(
    const float* __restrict__ src,      // [B,1,D]
    const float* __restrict__ Ww,       // [D,D]
    const float* __restrict__ Wt)       // [D,D]
{
    const float* Wm  = blockIdx.z ? Wt   : Ww;
    float*       out = blockIdx.z ? g_qt : g_qw;
    const int j  = blockIdx.x * 256 + threadIdx.x;
    const int i0 = blockIdx.y * 64;

    __shared__ float4 s4[B_][16];   // source slice: 16 batches x 64 i (as float4)
    {
        int b  = threadIdx.x >> 4;
        int ii = threadIdx.x & 15;
        s4[b][ii] = ((const float4*)(src + b * D_ + i0))[ii];
    }
    __syncthreads();

    float acc[B_];
    #pragma unroll
    for (int b = 0; b < B_; b++) acc[b] = 0.f;

    #pragma unroll 4
    for (int ig = 0; ig < 16; ig++) {
        const size_t row = (size_t)(i0 + ig * 4) * D_ + j;
        float w0 = Wm[row];
        float w1 = Wm[row + D_];
        float w2 = Wm[row + 2 * D_];
        float w3 = Wm[row + 3 * D_];
        #pragma unroll
        for (int b = 0; b < B_; b++) {
            float4 sv = s4[b][ig];
            acc[b] = fmaf(sv.x, w0, acc[b]);
            acc[b] = fmaf(sv.y, w1, acc[b]);
            acc[b] = fmaf(sv.z, w2, acc[b]);
            acc[b] = fmaf(sv.w, w3, acc[b]);
        }
    }
    #pragma unroll
    for (int b = 0; b < B_; b++) atomicAdd(&out[b * D_ + j], acc[b]);
}

// ---------------------------------------------------------------------------
// Kernel 2 (dominant): word-level attention per (b,t).
// Grid: B_*T_ = 512 blocks, 256 threads.
// Phase 1: scores for w < len only (skip masked rows -> ~half the HBM traffic)
// Phase 2: softmax over valid scores in smem
// Phase 3: cw = attn^T @ bank (tile is L2-resident) + turn-score dot
// ---------------------------------------------------------------------------
__global__ __launch_bounds__(256) void word_attn_kernel(
    const float* __restrict__ bank,     // [B,T,W,D]
    const int*   __restrict__ lengths)  // [B,T]
{
    const int bt  = blockIdx.x;
    const int b   = bt >> 5;            // T_ = 32
    const int len = lengths[bt];
    const float* base = bank + (size_t)bt * (W_ * D_);

    __shared__ float sh_q[D_];
    __shared__ float sh_s[W_];
    __shared__ float sh_red[8];

    const int tid  = threadIdx.x;
    const int warp = tid >> 5;
    const int lane = tid & 31;

    ((float4*)sh_q)[tid] = ((const float4*)(g_qw + b * D_))[tid];
    __syncthreads();

    // ---- Phase 1: scores for valid words only ----
    const float4* qp = (const float4*)sh_q;
    for (int w = warp; w < len; w += 8) {
        const float4* row = (const float4*)(base + (size_t)w * D_);
        float acc = 0.f;
        #pragma unroll
        for (int it = 0; it < 8; it++) {
            float4 v = row[it * 32 + lane];
            float4 q = qp[it * 32 + lane];
            acc += v.x * q.x + v.y * q.y + v.z * q.z + v.w * q.w;
        }
        #pragma unroll
        for (int off = 16; off; off >>= 1)
            acc += __shfl_xor_sync(0xffffffffu, acc, off);
        if (lane == 0) sh_s[w] = acc;
    }
    __syncthreads();

    // ---- Phase 2: softmax over sh_s[0..len) ----
    float s = (tid < len) ? sh_s[tid] : NEG_INF;
    float m = s;
    #pragma unroll
    for (int off = 16; off; off >>= 1)
        m = fmaxf(m, __shfl_xor_sync(0xffffffffu, m, off));
    if (lane == 0) sh_red[warp] = m;
    __syncthreads();
    if (tid == 0) {
        float mm = sh_red[0];
        #pragma unroll
        for (int i = 1; i < 8; i++) mm = fmaxf(mm, sh_red[i]);
        sh_red[0] = mm;
    }
    __syncthreads();
    m = sh_red[0];
    __syncthreads();

    float e = (tid < len) ? expf(s - m) : 0.f;
    float sum = e;
    #pragma unroll
    for (int off = 16; off; off >>= 1)
        sum += __shfl_xor_sync(0xffffffffu, sum, off);
    if (lane == 0) sh_red[warp] = sum;
    __syncthreads();
    if (tid == 0) {
        float tot = 0.f;
        #pragma unroll
        for (int i = 0; i < 8; i++) tot += sh_red[i];
        sh_red[0] = tot;
    }
    __syncthreads();
    float inv = 1.f / sh_red[0];
    if (tid < W_) sh_s[tid] = e * inv;   // e is 0 for masked words
    __syncthreads();

    // ---- Phase 3: cw = sum_w attn[w] * bank[w,:]  (L2-resident re-read) ----
    float4 acc = make_float4(0.f, 0.f, 0.f, 0.f);
    const float4* col = ((const float4*)base) + tid;   // stride 256 float4/row
    #pragma unroll 4
    for (int w = 0; w < len; w++) {
        float  a = sh_s[w];
        float4 v = col[(size_t)w * 256];
        acc.x = fmaf(a, v.x, acc.x);
        acc.y = fmaf(a, v.y, acc.y);
        acc.z = fmaf(a, v.z, acc.z);
        acc.w = fmaf(a, v.w, acc.w);
    }
    ((float4*)g_cw)[bt * 256 + tid] = acc;

    // Turn score: dot(q_t[b], cw)
    float4 qt = ((const float4*)(g_qt + b * D_))[tid];
    float p = acc.x * qt.x + acc.y * qt.y + acc.z * qt.z + acc.w * qt.w;
    #pragma unroll
    for (int off = 16; off; off >>= 1)
        p += __shfl_xor_sync(0xffffffffu, p, off);
    if (lane == 0) sh_red[warp] = p;
    __syncthreads();
    if (tid == 0) {
        float ts = 0.f;
        #pragma unroll
        for (int i = 0; i < 8; i++) ts += sh_red[i];
        g_ts[bt] = ts;
    }
}

// ---------------------------------------------------------------------------
// Kernel 3: turn-level softmax + weighted sum. Grid: B_ blocks, 256 threads.
// ---------------------------------------------------------------------------
__global__ __launch_bounds__(256) void turn_kernel(
    const int* __restrict__ turns,      // [B]
    float*     __restrict__ out)        // [B,D]
{
    const int b   = blockIdx.x;
    const int tid = threadIdx.x;
    __shared__ float sh_a[T_];
    __shared__ int   sh_nt;

    if (tid < 32) {
        int nt = turns[b];
        if (tid == 0) sh_nt = nt;
        float s = (tid < nt) ? g_ts[b * T_ + tid] : NEG_INF;
        float m = s;
        #pragma unroll
        for (int off = 16; off; off >>= 1)
            m = fmaxf(m, __shfl_xor_sync(0xffffffffu, m, off));
        float e = (tid < nt) ? expf(s - m) : 0.f;
        float sum = e;
        #pragma unroll
        for (int off = 16; off; off >>= 1)
            sum += __shfl_xor_sync(0xffffffffu, sum, off);
        sh_a[tid] = e / sum;
    }
    __syncthreads();

    const int nt = sh_nt;
    float4 acc = make_float4(0.f, 0.f, 0.f, 0.f);
    for (int t = 0; t < nt; t++) {
        float  a = sh_a[t];
        float4 v = ((const float4*)g_cw)[(b * T_ + t) * 256 + tid];
        acc.x = fmaf(a, v.x, acc.x);
        acc.y = fmaf(a, v.y, acc.y);
        acc.z = fmaf(a, v.z, acc.z);
        acc.w = fmaf(a, v.w, acc.w);
    }
    ((float4*)out)[b * 256 + tid] = acc;
}

// ---------------------------------------------------------------------------
// Launch: source, memory_bank, memory_lengths, memory_turns, W_word, W_turn
// ---------------------------------------------------------------------------
extern "C" void kernel_launch(void* const* d_in, const int* in_sizes, int n_in,
                              void* d_out, int out_size)
{
    (void)in_sizes; (void)n_in; (void)out_size;
    const float* source  = (const float*)d_in[0];
    const float* bank    = (const float*)d_in[1];
    const int*   lengths = (const int*)  d_in[2];
    const int*   turns   = (const int*)  d_in[3];
    const float* Wword   = (const float*)d_in[4];
    const float* Wturn   = (const float*)d_in[5];
    float*       out     = (float*)d_out;

    zero_q_kernel<<<16, 1024>>>();
    proj_kernel<<<dim3(D_ / 256, D_ / 64, 2), 256>>>(source, Wword, Wturn);
    word_attn_kernel<<<B_ * T_, 256>>>(bank, lengths);
    turn_kernel<<<B_, 256>>>(turns, out);
}

// round 7
// speedup vs baseline: 1.4218x; 1.4218x over previous
#include <cuda_runtime.h>
#include <math.h>

#define B_ 16
#define T_ 32
#define W_ 128
#define D_ 1024

#define NEG_BIG (-3.0e38f)

// Scratch (device globals: no allocation allowed in kernel_launch)
__device__ float g_qw[B_ * D_];          // source @ W_word   [B,D]
__device__ float g_qt[B_ * D_];          // source @ W_turn   [B,D]
__device__ float g_cw[B_ * T_ * D_];     // word-context      [B,T,D]
__device__ float g_ts[B_ * T_];          // turn scores       [B,T]

// ---------------------------------------------------------------------------
// Kernel 0: zero the projection accumulators (proj uses atomicAdd)
// ---------------------------------------------------------------------------
__global__ void zero_q_kernel() {
    int i = blockIdx.x * 1024 + threadIdx.x;   // 16 x 1024 = B_*D_
    g_qw[i] = 0.f;
    g_qt[i] = 0.f;
}

// ---------------------------------------------------------------------------
// Kernel 1: q = source @ W for both W_word and W_turn (unchanged — verified).
// Grid: (D_/256 j, D_/64 i, 2 matrices), 256 threads. W read once chip-wide.
// ---------------------------------------------------------------------------
__global__ __launch_bounds__(256) void proj_kernel(
    const float* __restrict__ src,      // [B,1,D]
    const float* __restrict__ Ww,       // [D,D]
    const float* __restrict__ Wt)       // [D,D]
{
    const float* Wm  = blockIdx.z ? Wt   : Ww;
    float*       out = blockIdx.z ? g_qt : g_qw;
    const int j  = blockIdx.x * 256 + threadIdx.x;
    const int i0 = blockIdx.y * 64;

    __shared__ float4 s4[B_][16];
    {
        int b  = threadIdx.x >> 4;
        int ii = threadIdx.x & 15;
        s4[b][ii] = ((const float4*)(src + b * D_ + i0))[ii];
    }
    __syncthreads();

    float acc[B_];
    #pragma unroll
    for (int b = 0; b < B_; b++) acc[b] = 0.f;

    #pragma unroll 4
    for (int ig = 0; ig < 16; ig++) {
        const size_t row = (size_t)(i0 + ig * 4) * D_ + j;
        float w0 = Wm[row];
        float w1 = Wm[row + D_];
        float w2 = Wm[row + 2 * D_];
        float w3 = Wm[row + 3 * D_];
        #pragma unroll
        for (int b = 0; b < B_; b++) {
            float4 sv = s4[b][ig];
            acc[b] = fmaf(sv.x, w0, acc[b]);
            acc[b] = fmaf(sv.y, w1, acc[b]);
            acc[b] = fmaf(sv.z, w2, acc[b]);
            acc[b] = fmaf(sv.w, w3, acc[b]);
        }
    }
    #pragma unroll
    for (int b = 0; b < B_; b++) atomicAdd(&out[b * D_ + j], acc[b]);
}

// ---------------------------------------------------------------------------
// Kernel 2 (dominant): fused single-pass word attention, one block per (b,t).
// 8 warps; warp w owns rows w, w+8, ... Each lane holds 8 float4 of the row
// (full 4 KB row register-resident per warp), so score + weighted-accumulate
// happen on ONE read of the row. Online softmax per warp (intra-warp shuffle
// reduce only — no per-row block barrier); warps merged once at the end.
// HBM traffic: each valid row read exactly once (~135 MB total).
// ---------------------------------------------------------------------------
__global__ __launch_bounds__(256, 2) void word_attn_kernel(
    const float* __restrict__ bank,     // [B,T,W,D]
    const int*   __restrict__ lengths)  // [B,T]
{
    const int bt  = blockIdx.x;
    const int b   = bt >> 5;            // T_ = 32
    const int len = lengths[bt];
    const float4* base = (const float4*)(bank + (size_t)bt * (W_ * D_)); // 256 f4/row

    const int tid  = threadIdx.x;
    const int warp = tid >> 5;
    const int lane = tid & 31;

    __shared__ float  sh_ml[8][2];      // per-warp (m, l) then reused for turn dot
    __shared__ float4 sh_cw[8 * 256];   // 32 KB: per-warp scaled accumulators

    // q_w slice, lane-strided layout: element k -> float4 index k*32+lane
    const float4* qw4 = (const float4*)(g_qw + b * D_);
    float4 q[8];
    #pragma unroll
    for (int k = 0; k < 8; k++) q[k] = qw4[k * 32 + lane];

    float  m = NEG_BIG, l = 0.f;
    float4 acc[8];
    #pragma unroll
    for (int k = 0; k < 8; k++) acc[k] = make_float4(0.f, 0.f, 0.f, 0.f);

    for (int w = warp; w < len; w += 8) {
        const float4* row = base + (size_t)w * 256;
        float4 v[8];
        #pragma unroll
        for (int k = 0; k < 8; k++) v[k] = row[k * 32 + lane];

        float p = 0.f;
        #pragma unroll
        for (int k = 0; k < 8; k++) {
            p = fmaf(v[k].x, q[k].x, p);
            p = fmaf(v[k].y, q[k].y, p);
            p = fmaf(v[k].z, q[k].z, p);
            p = fmaf(v[k].w, q[k].w, p);
        }
        #pragma unroll
        for (int off = 16; off; off >>= 1)
            p += __shfl_xor_sync(0xffffffffu, p, off);
        // p == full score s, in every lane

        float nm    = fmaxf(m, p);
        float alpha = __expf(m - nm);
        float e     = __expf(p - nm);
        l = l * alpha + e;
        #pragma unroll
        for (int k = 0; k < 8; k++) {
            acc[k].x = fmaf(acc[k].x, alpha, e * v[k].x);
            acc[k].y = fmaf(acc[k].y, alpha, e * v[k].y);
            acc[k].z = fmaf(acc[k].z, alpha, e * v[k].z);
            acc[k].w = fmaf(acc[k].w, alpha, e * v[k].w);
        }
        m = nm;
    }

    // ---- merge the 8 warps' online-softmax states ----
    if (lane == 0) { sh_ml[warp][0] = m; sh_ml[warp][1] = l; }
    __syncthreads();

    float gm = NEG_BIG;
    #pragma unroll
    for (int i = 0; i < 8; i++) gm = fmaxf(gm, sh_ml[i][0]);
    float gl = 0.f;
    #pragma unroll
    for (int i = 0; i < 8; i++) gl += sh_ml[i][1] * __expf(sh_ml[i][0] - gm);
    float scale = __expf(m - gm);    // 0 for warps that processed no rows

    #pragma unroll
    for (int k = 0; k < 8; k++) {
        float4 a = acc[k];
        sh_cw[warp * 256 + k * 32 + lane] =
            make_float4(a.x * scale, a.y * scale, a.z * scale, a.w * scale);
    }
    __syncthreads();

    float4 c = make_float4(0.f, 0.f, 0.f, 0.f);
    #pragma unroll
    for (int i = 0; i < 8; i++) {
        float4 a = sh_cw[i * 256 + tid];
        c.x += a.x; c.y += a.y; c.z += a.z; c.w += a.w;
    }
    float inv = 1.f / gl;
    c.x *= inv; c.y *= inv; c.z *= inv; c.w *= inv;
    ((float4*)g_cw)[bt * 256 + tid] = c;

    // ---- turn score: dot(q_t[b], cw) ----
    float4 qt = ((const float4*)(g_qt + b * D_))[tid];
    float p = c.x * qt.x + c.y * qt.y + c.z * qt.z + c.w * qt.w;
    #pragma unroll
    for (int off = 16; off; off >>= 1)
        p += __shfl_xor_sync(0xffffffffu, p, off);
    __syncthreads();                    // sh_ml reads above are done
    if (lane == 0) sh_ml[warp][0] = p;
    __syncthreads();
    if (tid == 0) {
        float ts = 0.f;
        #pragma unroll
        for (int i = 0; i < 8; i++) ts += sh_ml[i][0];
        g_ts[bt] = ts;
    }
}

// ---------------------------------------------------------------------------
// Kernel 3: turn-level softmax + weighted sum, now full-chip parallel.
// Grid: (8 D-chunks, B_) = 128 blocks, 256 threads. Turns split across warps.
// ---------------------------------------------------------------------------
__global__ __launch_bounds__(256) void turn_kernel(
    const int* __restrict__ turns,      // [B]
    float*     __restrict__ out)        // [B,D]
{
    const int b    = blockIdx.y;
    const int c    = blockIdx.x;        // chunk of 32 float4 (128 floats)
    const int tid  = threadIdx.x;
    const int warp = tid >> 5;
    const int lane = tid & 31;

    __shared__ float  sh_a[T_];
    __shared__ float4 sh_p[8][32];

    const int nt = turns[b];            // broadcast load

    if (warp == 0) {
        float s = (lane < nt) ? g_ts[b * T_ + lane] : NEG_BIG;
        float mm = s;
        #pragma unroll
        for (int off = 16; off; off >>= 1)
            mm = fmaxf(mm, __shfl_xor_sync(0xffffffffu, mm, off));
        float e = (lane < nt) ? __expf(s - mm) : 0.f;
        float sum = e;
        #pragma unroll
        for (int off = 16; off; off >>= 1)
            sum += __shfl_xor_sync(0xffffffffu, sum, off);
        sh_a[lane] = e / sum;
    }
    __syncthreads();

    float4 p = make_float4(0.f, 0.f, 0.f, 0.f);
    for (int t = warp; t < nt; t += 8) {
        float  a = sh_a[t];
        float4 v = ((const float4*)g_cw)[(b * T_ + t) * 256 + c * 32 + lane];
        p.x = fmaf(a, v.x, p.x);
        p.y = fmaf(a, v.y, p.y);
        p.z = fmaf(a, v.z, p.z);
        p.w = fmaf(a, v.w, p.w);
    }
    sh_p[warp][lane] = p;
    __syncthreads();

    if (warp == 0) {
        float4 s = sh_p[0][lane];
        #pragma unroll
        for (int i = 1; i < 8; i++) {
            float4 v = sh_p[i][lane];
            s.x += v.x; s.y += v.y; s.z += v.z; s.w += v.w;
        }
        ((float4*)out)[b * 256 + c * 32 + lane] = s;
    }
}

// ---------------------------------------------------------------------------
// Launch: source, memory_bank, memory_lengths, memory_turns, W_word, W_turn
// ---------------------------------------------------------------------------
extern "C" void kernel_launch(void* const* d_in, const int* in_sizes, int n_in,
                              void* d_out, int out_size)
{
    (void)in_sizes; (void)n_in; (void)out_size;
    const float* source  = (const float*)d_in[0];
    const float* bank    = (const float*)d_in[1];
    const int*   lengths = (const int*)  d_in[2];
    const int*   turns   = (const int*)  d_in[3];
    const float* Wword   = (const float*)d_in[4];
    const float* Wturn   = (const float*)d_in[5];
    float*       out     = (float*)d_out;

    zero_q_kernel<<<16, 1024>>>();
    proj_kernel<<<dim3(D_ / 256, D_ / 64, 2), 256>>>(source, Wword, Wturn);
    word_attn_kernel<<<B_ * T_, 256>>>(bank, lengths);
    turn_kernel<<<dim3(8, B_), 256>>>(turns, out);
}